// round 8
// baseline (speedup 1.0000x reference)
#include <cuda_runtime.h>
#include <cuda_bf16.h>
#include <cstdint>

#define T  1024
#define HD 2048
#define ID 4096
#define E  8

#define APITCH 40   // bf16 elems; 80B row pitch
#define BPITCH 72   // bf16 elems; 144B row pitch
#define NK1 (HD / 32)
#define NK2 (ID / 32)

// double-buffer smem layout (bytes)
#define GU_AH  0
#define GU_AL  10240
#define GU_B0H 20480
#define GU_B1H 25088
#define GU_B0L 29696
#define GU_B1L 34304
#define GU_SS  38912
#define GU_BYTES (2 * GU_SS)

#define DN_AH  0
#define DN_AL  10240
#define DN_BH  20480
#define DN_BL  25088
#define DN_SS  29696
#define DN_BYTES (2 * DN_SS)

// ---- scratch ----
__device__ __nv_bfloat16 g_x_hi[(size_t)T * HD];
__device__ __nv_bfloat16 g_x_lo[(size_t)T * HD];
__device__ __nv_bfloat16 g_xr_hi[(size_t)E * 1024 * HD];
__device__ __nv_bfloat16 g_xr_lo[(size_t)E * 1024 * HD];
__device__ __nv_bfloat16 g_hs_hi[(size_t)T * ID];
__device__ __nv_bfloat16 g_hs_lo[(size_t)T * ID];
__device__ __nv_bfloat16 g_hr_hi[(size_t)E * 1024 * ID];
__device__ __nv_bfloat16 g_hr_lo[(size_t)E * 1024 * ID];
__device__ int   g_expert[T];
__device__ float g_score[T];
__device__ int   g_perm[T];
__device__ int   g_offsets[E + 1];

// ---- helpers ----
__device__ __forceinline__ uint32_t smem_u32(const void* p) {
    uint32_t a;
    asm("{ .reg .u64 t; cvta.to.shared.u64 t, %1; cvt.u32.u64 %0, t; }" : "=r"(a) : "l"(p));
    return a;
}
__device__ __forceinline__ void ldsm4(uint32_t* r, uint32_t a) {
    asm volatile("ldmatrix.sync.aligned.m8n8.x4.shared.b16 {%0,%1,%2,%3}, [%4];"
                 : "=r"(r[0]), "=r"(r[1]), "=r"(r[2]), "=r"(r[3]) : "r"(a));
}
__device__ __forceinline__ void ldsm4t(uint32_t* r, uint32_t a) {
    asm volatile("ldmatrix.sync.aligned.m8n8.x4.trans.shared.b16 {%0,%1,%2,%3}, [%4];"
                 : "=r"(r[0]), "=r"(r[1]), "=r"(r[2]), "=r"(r[3]) : "r"(a));
}
__device__ __forceinline__ void mma_bf16(float* c, const uint32_t* a, const uint32_t* b) {
    asm volatile("mma.sync.aligned.m16n8k16.row.col.f32.bf16.bf16.f32 "
                 "{%0,%1,%2,%3}, {%4,%5,%6,%7}, {%8,%9}, {%0,%1,%2,%3};"
                 : "+f"(c[0]), "+f"(c[1]), "+f"(c[2]), "+f"(c[3])
                 : "r"(a[0]), "r"(a[1]), "r"(a[2]), "r"(a[3]), "r"(b[0]), "r"(b[1]));
}
__device__ __forceinline__ void split_bf16(float v, __nv_bfloat16& h, __nv_bfloat16& l) {
    h = __float2bfloat16_rn(v);
    l = __float2bfloat16_rn(v - __bfloat162float(h));
}
__device__ __forceinline__ uint32_t pack2(__nv_bfloat16 a, __nv_bfloat16 b) {
    __nv_bfloat162 t = __halves2bfloat162(a, b);
    return *(uint32_t*)&t;
}
__device__ __forceinline__ void split8(float4 v0, float4 v1,
                                       __nv_bfloat16* dh, __nv_bfloat16* dl) {
    float f[8] = {v0.x, v0.y, v0.z, v0.w, v1.x, v1.y, v1.z, v1.w};
    uint32_t H[4], L[4];
#pragma unroll
    for (int i = 0; i < 4; i++) {
        __nv_bfloat16 h0, l0, h1, l1;
        split_bf16(f[2*i], h0, l0);
        split_bf16(f[2*i+1], h1, l1);
        H[i] = pack2(h0, h1);
        L[i] = pack2(l0, l1);
    }
    *(uint4*)dh = make_uint4(H[0], H[1], H[2], H[3]);
    *(uint4*)dl = make_uint4(L[0], L[1], L[2], L[3]);
}

// ============================================================================
__global__ void router_kernel(const float* __restrict__ x, const float* __restrict__ wr) {
    int warp = (blockIdx.x * blockDim.x + threadIdx.x) >> 5;
    int lane = threadIdx.x & 31;
    if (warp >= T) return;
    const float* xr = x + (size_t)warp * HD;
    float acc[E];
#pragma unroll
    for (int e = 0; e < E; e++) acc[e] = 0.f;
    for (int h = lane; h < HD; h += 32) {
        float xv = xr[h];
        const float* w = wr + (size_t)h * E;
#pragma unroll
        for (int e = 0; e < E; e++) acc[e] += xv * w[e];
    }
#pragma unroll
    for (int e = 0; e < E; e++) {
#pragma unroll
        for (int o = 16; o; o >>= 1) acc[e] += __shfl_xor_sync(0xffffffffu, acc[e], o);
    }
    if (lane == 0) {
        int best = 0; float bv = acc[0];
#pragma unroll
        for (int e = 1; e < E; e++) if (acc[e] > bv) { bv = acc[e]; best = e; }
        g_expert[warp] = best;
        g_score[warp]  = 1.f / (1.f + __expf(-bv));
    }
}

__global__ void perm_kernel() {
    __shared__ int cnt[E], off[E + 1], cur[E];
    int t = threadIdx.x;
    if (t < E) cnt[t] = 0;
    __syncthreads();
    int e = g_expert[t];
    atomicAdd(&cnt[e], 1);
    __syncthreads();
    if (t == 0) {
        off[0] = 0;
        for (int i = 0; i < E; i++) off[i + 1] = off[i] + cnt[i];
    }
    __syncthreads();
    if (t < E) cur[t] = off[t];
    __syncthreads();
    int pos = atomicAdd(&cur[e], 1);
    g_perm[pos] = t;
    if (t <= E) g_offsets[t] = off[t];
}

__global__ void presplit_x(const float* __restrict__ x) {
    int idx = blockIdx.x * 256 + threadIdx.x;
    float4 v = *(const float4*)(x + (size_t)idx * 4);
    __nv_bfloat16 h0,l0,h1,l1,h2,l2,h3,l3;
    split_bf16(v.x,h0,l0); split_bf16(v.y,h1,l1); split_bf16(v.z,h2,l2); split_bf16(v.w,h3,l3);
    *(uint2*)(g_x_hi + (size_t)idx * 4) = make_uint2(pack2(h0,h1), pack2(h2,h3));
    *(uint2*)(g_x_lo + (size_t)idx * 4) = make_uint2(pack2(l0,l1), pack2(l2,l3));
}

__global__ void gather_kernel(const float* __restrict__ x) {
    int e = blockIdx.y;
    int obase = g_offsets[e], cnt = g_offsets[e + 1] - obase;
    int pad = (cnt + 255) & ~255;
    int r0 = blockIdx.x * 16;
    if (r0 >= pad) return;
    for (int idx = threadIdx.x; idx < 16 * HD / 4; idx += 256) {
        int row = idx >> 9;
        int c4  = (idx & 511) * 4;
        int r = r0 + row;
        uint2 hv = make_uint2(0u, 0u), lv = make_uint2(0u, 0u);
        if (r < cnt) {
            int tok = g_perm[obase + r];
            float sc = g_score[tok];
            float4 v = *(const float4*)(x + (size_t)tok * HD + c4);
            v.x *= sc; v.y *= sc; v.z *= sc; v.w *= sc;
            __nv_bfloat16 h0,l0,h1,l1,h2,l2,h3,l3;
            split_bf16(v.x,h0,l0); split_bf16(v.y,h1,l1); split_bf16(v.z,h2,l2); split_bf16(v.w,h3,l3);
            hv = make_uint2(pack2(h0,h1), pack2(h2,h3));
            lv = make_uint2(pack2(l0,l1), pack2(l2,l3));
        }
        size_t go = (size_t)(e * 1024 + r) * HD + c4;
        *(uint2*)(g_xr_hi + go) = hv;
        *(uint2*)(g_xr_lo + go) = lv;
    }
}

// ============================================================================
// GEMM1 fused (z=0 shared, z=1..E experts): 512 threads, 16 warps (4m x 4n),
// warp tile 32x16 per matrix; split-bf16 3-term; double-buffered, 1 sync/tile.
// ============================================================================
__global__ __launch_bounds__(512)
void gateup_kernel(const float* __restrict__ Wgs, const float* __restrict__ Wus,
                   const float* __restrict__ Wge, const float* __restrict__ Wue) {
    extern __shared__ char smem[];

    int tid = threadIdx.x, wid = tid >> 5, lane = tid & 31;
    int z = blockIdx.z;

    int cnt; size_t arow0;
    const float *wg, *wu;
    const __nv_bfloat16 *axh, *axl;
    __nv_bfloat16 *ohh, *ohl;
    if (z > 0) {
        int e = z - 1;
        cnt = g_offsets[e + 1] - g_offsets[e];
        wg = Wge + (size_t)e * HD * ID; wu = Wue + (size_t)e * HD * ID;
        axh = g_xr_hi; axl = g_xr_lo; ohh = g_hr_hi; ohl = g_hr_lo;
        arow0 = (size_t)e * 1024;
    } else {
        cnt = T; wg = Wgs; wu = Wus;
        axh = g_x_hi; axl = g_x_lo; ohh = g_hs_hi; ohl = g_hs_lo;
        arow0 = 0;
    }
    int m0 = blockIdx.x * 128;
    if (m0 >= cnt) return;
    int n0 = blockIdx.y * 64;

    // staging: A 8 bf16 (hi+lo) per thread; B 8 fp32 per thread (one matrix)
    int sa_row = tid >> 2, sa_col = (tid & 3) * 8;
    const __nv_bfloat16* pAh = axh + (arow0 + m0 + sa_row) * HD + sa_col;
    const __nv_bfloat16* pAl = axl + (arow0 + m0 + sa_row) * HD + sa_col;
    int bmat = tid >> 8, sb_k = (tid >> 3) & 31, sb_j = (tid & 7) * 8;
    const float* pB = (bmat ? wu : wg) + (size_t)sb_k * ID + n0 + sb_j;
    int a_boff = (sa_row * APITCH + sa_col) * 2;
    int b_boff = (sb_k * BPITCH + sb_j) * 2;
    int bh_off = bmat ? GU_B1H : GU_B0H;
    int bl_off = bmat ? GU_B1L : GU_B0L;

    // MMA indices: 16 warps -> 4m x 4n, warp tile 32x16
    int wm = (wid >> 2) * 32, wn = (wid & 3) * 16;
    uint32_t sbase = smem_u32(smem);
    int a_lr = lane & 15, a_lc = (lane >> 4) * 8;
    int b_lk = (lane & 7) + (lane >> 4) * 8, b_ln = ((lane >> 3) & 1) * 8;

    float accg[2][2][4] = {}, accu[2][2][4] = {};

    uint4 a_h0, a_l0;
    float4 f_b0, f_b1;
#define GU_LDG(it) { \
    a_h0 = *(const uint4*)(pAh + (it) * 32); \
    a_l0 = *(const uint4*)(pAl + (it) * 32); \
    const float* pb = pB + (size_t)(it) * 32 * ID; \
    f_b0 = *(const float4*)pb; f_b1 = *(const float4*)(pb + 4); }
#define GU_STS(st) { \
    char* base = smem + (st) * GU_SS; \
    *(uint4*)(base + GU_AH + a_boff) = a_h0; \
    *(uint4*)(base + GU_AL + a_boff) = a_l0; \
    split8(f_b0, f_b1, (__nv_bfloat16*)(base + bh_off + b_boff), (__nv_bfloat16*)(base + bl_off + b_boff)); }

    GU_LDG(0);
    GU_STS(0);
    GU_LDG(1);
    __syncthreads();

    int st = 0;
    for (int it = 0; it < NK1; it++) {
        if (it + 1 < NK1) {
            GU_STS(st ^ 1);
            if (it + 2 < NK1) GU_LDG(it + 2);
        }
        uint32_t sb = sbase + st * GU_SS;
#pragma unroll
        for (int kk = 0; kk < 32; kk += 16) {
            uint32_t ah[2][4], al2[2][4];
#pragma unroll
            for (int mi = 0; mi < 2; mi++) {
                uint32_t ao = (uint32_t)((wm + mi * 16 + a_lr) * APITCH + kk + a_lc) * 2;
                ldsm4(ah[mi], sb + GU_AH + ao);
                ldsm4(al2[mi], sb + GU_AL + ao);
            }
            uint32_t bo = (uint32_t)((kk + b_lk) * BPITCH + wn + b_ln) * 2;
#pragma unroll
            for (int mat = 0; mat < 2; mat++) {
                uint32_t r[4], bh[2][2], bl2[2][2];
                ldsm4t(r, sb + (mat ? GU_B1H : GU_B0H) + bo);
                bh[0][0] = r[0]; bh[0][1] = r[2];
                bh[1][0] = r[1]; bh[1][1] = r[3];
                ldsm4t(r, sb + (mat ? GU_B1L : GU_B0L) + bo);
                bl2[0][0] = r[0]; bl2[0][1] = r[2];
                bl2[1][0] = r[1]; bl2[1][1] = r[3];
                float (*acc)[2][4] = mat ? accu : accg;
#pragma unroll
                for (int mi = 0; mi < 2; mi++)
#pragma unroll
                    for (int ni = 0; ni < 2; ni++) {
                        mma_bf16(acc[mi][ni], ah[mi], bh[ni]);
                        mma_bf16(acc[mi][ni], ah[mi], bl2[ni]);
                        mma_bf16(acc[mi][ni], al2[mi], bh[ni]);
                    }
            }
        }
        __syncthreads();
        st ^= 1;
    }
#undef GU_LDG
#undef GU_STS

    // epilogue
    int er = lane >> 2, ec = (lane & 3) * 2;
#pragma unroll
    for (int mi = 0; mi < 2; mi++) {
#pragma unroll
        for (int half = 0; half < 2; half++) {
            size_t row = arow0 + m0 + wm + mi * 16 + er + half * 8;
#pragma unroll
            for (int ni = 0; ni < 2; ni++) {
                int c = n0 + wn + ni * 8 + ec;
                float g0 = accg[mi][ni][half*2],     u0 = accu[mi][ni][half*2];
                float g1 = accg[mi][ni][half*2 + 1], u1 = accu[mi][ni][half*2 + 1];
                float f0 = (g0 / (1.f + __expf(-g0))) * u0;
                float f1 = (g1 / (1.f + __expf(-g1))) * u1;
                __nv_bfloat16 h0, l0, h1, l1;
                split_bf16(f0, h0, l0); split_bf16(f1, h1, l1);
                *(uint32_t*)(ohh + row * ID + c) = pack2(h0, h1);
                *(uint32_t*)(ohl + row * ID + c) = pack2(l0, l1);
            }
        }
    }
}

// ============================================================================
// GEMM2: 512 threads, 16 warps (4m x 4n), warp tile 32x16; double-buffered.
// shared pass writes out; routed pass (after) does +=.
// ============================================================================
__global__ __launch_bounds__(512)
void down_kernel(const float* __restrict__ Wd, float* __restrict__ out, int routed) {
    extern __shared__ char smem[];

    int tid = threadIdx.x, wid = tid >> 5, lane = tid & 31;

    int cnt, obase; size_t arow0;
    const float* wd;
    const __nv_bfloat16 *axh, *axl;
    if (routed) {
        int e = blockIdx.z;
        obase = g_offsets[e]; cnt = g_offsets[e + 1] - obase;
        wd = Wd + (size_t)e * ID * HD;
        axh = g_hr_hi; axl = g_hr_lo;
        arow0 = (size_t)e * 1024;
    } else {
        obase = 0; cnt = T; wd = Wd;
        axh = g_hs_hi; axl = g_hs_lo;
        arow0 = 0;
    }
    int m0 = blockIdx.x * 128;
    if (m0 >= cnt) return;
    int n0 = blockIdx.y * 64;

    int sa_row = tid >> 2, sa_col = (tid & 3) * 8;
    const __nv_bfloat16* pAh = axh + (arow0 + m0 + sa_row) * ID + sa_col;
    const __nv_bfloat16* pAl = axl + (arow0 + m0 + sa_row) * ID + sa_col;
    int sb_k = (tid >> 3) & 31, sb_j = (tid & 7) * 8;
    const float* pW = wd + (size_t)sb_k * HD + n0 + sb_j;
    int a_boff = (sa_row * APITCH + sa_col) * 2;
    int b_boff = (sb_k * BPITCH + sb_j) * 2;
    bool do_b = (tid < 256);

    int wm = (wid >> 2) * 32, wn = (wid & 3) * 16;
    uint32_t sbase = smem_u32(smem);
    int a_lr = lane & 15, a_lc = (lane >> 4) * 8;
    int b_lk = (lane & 7) + (lane >> 4) * 8, b_ln = ((lane >> 3) & 1) * 8;

    float acc[2][2][4] = {};

    uint4 a_h0, a_l0;
    float4 f_w0, f_w1;
#define DN_LDG(it) { \
    a_h0 = *(const uint4*)(pAh + (it) * 32); \
    a_l0 = *(const uint4*)(pAl + (it) * 32); \
    if (do_b) { \
        const float* pw = pW + (size_t)(it) * 32 * HD; \
        f_w0 = *(const float4*)pw; f_w1 = *(const float4*)(pw + 4); } }
#define DN_STS(st) { \
    char* base = smem + (st) * DN_SS; \
    *(uint4*)(base + DN_AH + a_boff) = a_h0; \
    *(uint4*)(base + DN_AL + a_boff) = a_l0; \
    if (do_b) split8(f_w0, f_w1, (__nv_bfloat16*)(base + DN_BH + b_boff), (__nv_bfloat16*)(base + DN_BL + b_boff)); }

    DN_LDG(0);
    DN_STS(0);
    DN_LDG(1);
    __syncthreads();

    int st = 0;
    for (int it = 0; it < NK2; it++) {
        if (it + 1 < NK2) {
            DN_STS(st ^ 1);
            if (it + 2 < NK2) DN_LDG(it + 2);
        }
        uint32_t sb = sbase + st * DN_SS;
#pragma unroll
        for (int kk = 0; kk < 32; kk += 16) {
            uint32_t ah[2][4], al2[2][4];
#pragma unroll
            for (int mi = 0; mi < 2; mi++) {
                uint32_t ao = (uint32_t)((wm + mi * 16 + a_lr) * APITCH + kk + a_lc) * 2;
                ldsm4(ah[mi], sb + DN_AH + ao);
                ldsm4(al2[mi], sb + DN_AL + ao);
            }
            uint32_t bo = (uint32_t)((kk + b_lk) * BPITCH + wn + b_ln) * 2;
            uint32_t r[4], bh[2][2], bl2[2][2];
            ldsm4t(r, sb + DN_BH + bo);
            bh[0][0] = r[0]; bh[0][1] = r[2];
            bh[1][0] = r[1]; bh[1][1] = r[3];
            ldsm4t(r, sb + DN_BL + bo);
            bl2[0][0] = r[0]; bl2[0][1] = r[2];
            bl2[1][0] = r[1]; bl2[1][1] = r[3];
#pragma unroll
            for (int mi = 0; mi < 2; mi++)
#pragma unroll
                for (int ni = 0; ni < 2; ni++) {
                    mma_bf16(acc[mi][ni], ah[mi], bh[ni]);
                    mma_bf16(acc[mi][ni], ah[mi], bl2[ni]);
                    mma_bf16(acc[mi][ni], al2[mi], bh[ni]);
                }
        }
        __syncthreads();
        st ^= 1;
    }
#undef DN_LDG
#undef DN_STS

    int er = lane >> 2, ec = (lane & 3) * 2;
#pragma unroll
    for (int mi = 0; mi < 2; mi++) {
#pragma unroll
        for (int half = 0; half < 2; half++) {
            int gr = m0 + wm + mi * 16 + er + half * 8;
            int token = -1;
            if (gr < cnt) token = routed ? g_perm[obase + gr] : gr;
            if (token >= 0) {
#pragma unroll
                for (int ni = 0; ni < 2; ni++) {
                    int c = n0 + wn + ni * 8 + ec;
                    float2 v = make_float2(acc[mi][ni][half*2], acc[mi][ni][half*2 + 1]);
                    float2* p = (float2*)(out + (size_t)token * HD + c);
                    if (routed) { float2 o = *p; v.x += o.x; v.y += o.y; }
                    *p = v;
                }
            }
        }
    }
}

// ============================================================================
extern "C" void kernel_launch(void* const* d_in, const int* in_sizes, int n_in,
                              void* d_out, int out_size) {
    const float* x        = (const float*)d_in[0];
    const float* w_router = (const float*)d_in[1];
    const float* ws_gate  = (const float*)d_in[2];
    const float* ws_up    = (const float*)d_in[3];
    const float* ws_down  = (const float*)d_in[4];
    const float* we_gate  = (const float*)d_in[5];
    const float* we_up    = (const float*)d_in[6];
    const float* we_down  = (const float*)d_in[7];
    float* out = (float*)d_out;
    (void)in_sizes; (void)n_in; (void)out_size;

    cudaFuncSetAttribute(gateup_kernel, cudaFuncAttributeMaxDynamicSharedMemorySize, GU_BYTES);
    cudaFuncSetAttribute(down_kernel,   cudaFuncAttributeMaxDynamicSharedMemorySize, DN_BYTES);

    router_kernel<<<T / 8, 256>>>(x, w_router);
    perm_kernel<<<1, T>>>();
    presplit_x<<<T * HD / 4 / 256, 256>>>(x);
    gather_kernel<<<dim3(64, E), 256>>>(x);

    gateup_kernel<<<dim3(T / 128, ID / 64, E + 1), 512, GU_BYTES>>>(ws_gate, ws_up, we_gate, we_up);

    down_kernel<<<dim3(T / 128, HD / 64, 1), 512, DN_BYTES>>>(ws_down, out, 0);
    down_kernel<<<dim3(T / 128, HD / 64, E), 512, DN_BYTES>>>(we_down, out, 1);
}

// round 9
// speedup vs baseline: 1.3356x; 1.3356x over previous
#include <cuda_runtime.h>
#include <cuda_fp16.h>
#include <cstdint>

#define T  1024
#define HD 2048
#define ID 4096
#define E  8

#define APITCH 40   // fp16 elems; 80B row pitch (conflict-free for ldmatrix)
#define BPITCH 72   // fp16 elems; 144B row pitch
#define NK1 (HD / 32)
#define NK2 (ID / 32)

// double-buffer smem layout (bytes)
#define GU_AH  0
#define GU_AL  10240
#define GU_B0  20480
#define GU_B1  25088
#define GU_SS  29696
#define GU_BYTES (2 * GU_SS)

#define DN_AH  0
#define DN_AL  10240
#define DN_B   20480
#define DN_SS  25088
#define DN_BYTES (2 * DN_SS)

// ---- scratch (fp16 hi/lo pairs) ----
__device__ __half g_x_hi[(size_t)T * HD];
__device__ __half g_x_lo[(size_t)T * HD];
__device__ __half g_xr_hi[(size_t)E * 1024 * HD];
__device__ __half g_xr_lo[(size_t)E * 1024 * HD];
__device__ __half g_hs_hi[(size_t)T * ID];
__device__ __half g_hs_lo[(size_t)T * ID];
__device__ __half g_hr_hi[(size_t)E * 1024 * ID];
__device__ __half g_hr_lo[(size_t)E * 1024 * ID];
__device__ int   g_expert[T];
__device__ float g_score[T];
__device__ int   g_perm[T];
__device__ int   g_offsets[E + 1];

// ---- helpers ----
__device__ __forceinline__ uint32_t smem_u32(const void* p) {
    uint32_t a;
    asm("{ .reg .u64 t; cvta.to.shared.u64 t, %1; cvt.u32.u64 %0, t; }" : "=r"(a) : "l"(p));
    return a;
}
__device__ __forceinline__ void ldsm4(uint32_t* r, uint32_t a) {
    asm volatile("ldmatrix.sync.aligned.m8n8.x4.shared.b16 {%0,%1,%2,%3}, [%4];"
                 : "=r"(r[0]), "=r"(r[1]), "=r"(r[2]), "=r"(r[3]) : "r"(a));
}
__device__ __forceinline__ void ldsm4t(uint32_t* r, uint32_t a) {
    asm volatile("ldmatrix.sync.aligned.m8n8.x4.trans.shared.b16 {%0,%1,%2,%3}, [%4];"
                 : "=r"(r[0]), "=r"(r[1]), "=r"(r[2]), "=r"(r[3]) : "r"(a));
}
__device__ __forceinline__ void mma_f16(float* c, const uint32_t* a, const uint32_t* b) {
    asm volatile("mma.sync.aligned.m16n8k16.row.col.f32.f16.f16.f32 "
                 "{%0,%1,%2,%3}, {%4,%5,%6,%7}, {%8,%9}, {%0,%1,%2,%3};"
                 : "+f"(c[0]), "+f"(c[1]), "+f"(c[2]), "+f"(c[3])
                 : "r"(a[0]), "r"(a[1]), "r"(a[2]), "r"(a[3]), "r"(b[0]), "r"(b[1]));
}
__device__ __forceinline__ void split_f16(float v, __half& h, __half& l) {
    h = __float2half_rn(v);
    l = __float2half_rn(v - __half2float(h));
}
__device__ __forceinline__ uint32_t pack2(__half a, __half b) {
    __half2 t = __halves2half2(a, b);
    return *(uint32_t*)&t;
}
// 8 fp32 -> 8 fp16 (single rounding), one uint4
__device__ __forceinline__ void cvt8(float4 v0, float4 v1, __half* d) {
    float f[8] = {v0.x, v0.y, v0.z, v0.w, v1.x, v1.y, v1.z, v1.w};
    uint32_t H[4];
#pragma unroll
    for (int i = 0; i < 4; i++)
        H[i] = pack2(__float2half_rn(f[2*i]), __float2half_rn(f[2*i+1]));
    *(uint4*)d = make_uint4(H[0], H[1], H[2], H[3]);
}

// ============================================================================
__global__ void router_kernel(const float* __restrict__ x, const float* __restrict__ wr) {
    int warp = (blockIdx.x * blockDim.x + threadIdx.x) >> 5;
    int lane = threadIdx.x & 31;
    if (warp >= T) return;
    const float* xr = x + (size_t)warp * HD;
    float acc[E];
#pragma unroll
    for (int e = 0; e < E; e++) acc[e] = 0.f;
    for (int h = lane; h < HD; h += 32) {
        float xv = xr[h];
        const float* w = wr + (size_t)h * E;
#pragma unroll
        for (int e = 0; e < E; e++) acc[e] += xv * w[e];
    }
#pragma unroll
    for (int e = 0; e < E; e++) {
#pragma unroll
        for (int o = 16; o; o >>= 1) acc[e] += __shfl_xor_sync(0xffffffffu, acc[e], o);
    }
    if (lane == 0) {
        int best = 0; float bv = acc[0];
#pragma unroll
        for (int e = 1; e < E; e++) if (acc[e] > bv) { bv = acc[e]; best = e; }
        g_expert[warp] = best;
        g_score[warp]  = 1.f / (1.f + __expf(-bv));
    }
}

__global__ void perm_kernel() {
    __shared__ int cnt[E], off[E + 1], cur[E];
    int t = threadIdx.x;
    if (t < E) cnt[t] = 0;
    __syncthreads();
    int e = g_expert[t];
    atomicAdd(&cnt[e], 1);
    __syncthreads();
    if (t == 0) {
        off[0] = 0;
        for (int i = 0; i < E; i++) off[i + 1] = off[i] + cnt[i];
    }
    __syncthreads();
    if (t < E) cur[t] = off[t];
    __syncthreads();
    int pos = atomicAdd(&cur[e], 1);
    g_perm[pos] = t;
    if (t <= E) g_offsets[t] = off[t];
}

__global__ void presplit_x(const float* __restrict__ x) {
    int idx = blockIdx.x * 256 + threadIdx.x;
    float4 v = *(const float4*)(x + (size_t)idx * 4);
    __half h0,l0,h1,l1,h2,l2,h3,l3;
    split_f16(v.x,h0,l0); split_f16(v.y,h1,l1); split_f16(v.z,h2,l2); split_f16(v.w,h3,l3);
    *(uint2*)(g_x_hi + (size_t)idx * 4) = make_uint2(pack2(h0,h1), pack2(h2,h3));
    *(uint2*)(g_x_lo + (size_t)idx * 4) = make_uint2(pack2(l0,l1), pack2(l2,l3));
}

__global__ void gather_kernel(const float* __restrict__ x) {
    int e = blockIdx.y;
    int obase = g_offsets[e], cnt = g_offsets[e + 1] - obase;
    int pad = (cnt + 255) & ~255;
    int r0 = blockIdx.x * 16;
    if (r0 >= pad) return;
    for (int idx = threadIdx.x; idx < 16 * HD / 4; idx += 256) {
        int row = idx >> 9;
        int c4  = (idx & 511) * 4;
        int r = r0 + row;
        uint2 hv = make_uint2(0u, 0u), lv = make_uint2(0u, 0u);
        if (r < cnt) {
            int tok = g_perm[obase + r];
            float sc = g_score[tok];
            float4 v = *(const float4*)(x + (size_t)tok * HD + c4);
            v.x *= sc; v.y *= sc; v.z *= sc; v.w *= sc;
            __half h0,l0,h1,l1,h2,l2,h3,l3;
            split_f16(v.x,h0,l0); split_f16(v.y,h1,l1); split_f16(v.z,h2,l2); split_f16(v.w,h3,l3);
            hv = make_uint2(pack2(h0,h1), pack2(h2,h3));
            lv = make_uint2(pack2(l0,l1), pack2(l2,l3));
        }
        size_t go = (size_t)(e * 1024 + r) * HD + c4;
        *(uint2*)(g_xr_hi + go) = hv;
        *(uint2*)(g_xr_lo + go) = lv;
    }
}

// ============================================================================
// GEMM1: h = silu(A@Wg) * (A@Wu). BM=128, BN=64, BK=32; 8 warps (4m x 2n),
// warp tile 32x32 per matrix; fp16 2-term (A hi/lo, B single); double-buffered.
// ============================================================================
__global__ __launch_bounds__(256)
void gateup_kernel(const float* __restrict__ Wg, const float* __restrict__ Wu, int routed) {
    extern __shared__ char smem[];

    int tid = threadIdx.x, wid = tid >> 5, lane = tid & 31;

    int cnt; size_t arow0;
    const float *wg, *wu;
    const __half *axh, *axl;
    __half *ohh, *ohl;
    if (routed) {
        int e = blockIdx.z;
        cnt = g_offsets[e + 1] - g_offsets[e];
        wg = Wg + (size_t)e * HD * ID; wu = Wu + (size_t)e * HD * ID;
        axh = g_xr_hi; axl = g_xr_lo; ohh = g_hr_hi; ohl = g_hr_lo;
        arow0 = (size_t)e * 1024;
    } else {
        cnt = T; wg = Wg; wu = Wu;
        axh = g_x_hi; axl = g_x_lo; ohh = g_hs_hi; ohl = g_hs_lo;
        arow0 = 0;
    }
    int m0 = blockIdx.x * 128;
    if (m0 >= cnt) return;
    int n0 = blockIdx.y * 64;

    int sa_row = tid >> 1, sa_col = (tid & 1) * 16;
    const __half* pAh = axh + (arow0 + m0 + sa_row) * HD + sa_col;
    const __half* pAl = axl + (arow0 + m0 + sa_row) * HD + sa_col;
    int sb_k = tid >> 3, sb_j = (tid & 7) * 8;
    const float* pG = wg + (size_t)sb_k * ID + n0 + sb_j;
    const float* pU = wu + (size_t)sb_k * ID + n0 + sb_j;
    int a_boff = (sa_row * APITCH + sa_col) * 2;
    int b_boff = (sb_k * BPITCH + sb_j) * 2;

    int wm = (wid >> 1) * 32, wn = (wid & 1) * 32;
    uint32_t sbase = smem_u32(smem);
    int a_lr = lane & 15, a_lc = (lane >> 4) * 8;
    int b_lk = (lane & 7) + (lane >> 4) * 8, b_ln = ((lane >> 3) & 1) * 8;

    float accg[2][4][4] = {}, accu[2][4][4] = {};

    uint4 a_h0, a_h1, a_l0, a_l1;
    float4 f_g0, f_g1, f_u0, f_u1;
#define GU_LDG(it) { \
    const __half* ph = pAh + (it) * 32; \
    a_h0 = *(const uint4*)ph; a_h1 = *(const uint4*)(ph + 8); \
    const __half* pl = pAl + (it) * 32; \
    a_l0 = *(const uint4*)pl; a_l1 = *(const uint4*)(pl + 8); \
    const float* pg = pG + (size_t)(it) * 32 * ID; \
    f_g0 = *(const float4*)pg; f_g1 = *(const float4*)(pg + 4); \
    const float* pu = pU + (size_t)(it) * 32 * ID; \
    f_u0 = *(const float4*)pu; f_u1 = *(const float4*)(pu + 4); }
#define GU_STS(st) { \
    char* base = smem + (st) * GU_SS; \
    *(uint4*)(base + GU_AH + a_boff) = a_h0; \
    *(uint4*)(base + GU_AH + a_boff + 16) = a_h1; \
    *(uint4*)(base + GU_AL + a_boff) = a_l0; \
    *(uint4*)(base + GU_AL + a_boff + 16) = a_l1; \
    cvt8(f_g0, f_g1, (__half*)(base + GU_B0 + b_boff)); \
    cvt8(f_u0, f_u1, (__half*)(base + GU_B1 + b_boff)); }

    GU_LDG(0);
    GU_STS(0);
    GU_LDG(1);
    __syncthreads();

    int st = 0;
    for (int it = 0; it < NK1; it++) {
        if (it + 1 < NK1) {
            GU_STS(st ^ 1);
            if (it + 2 < NK1) GU_LDG(it + 2);
        }
        uint32_t sb = sbase + st * GU_SS;
#pragma unroll
        for (int kk = 0; kk < 32; kk += 16) {
            uint32_t ah[2][4], al2[2][4];
#pragma unroll
            for (int mi = 0; mi < 2; mi++) {
                uint32_t ao = (uint32_t)((wm + mi * 16 + a_lr) * APITCH + kk + a_lc) * 2;
                ldsm4(ah[mi], sb + GU_AH + ao);
                ldsm4(al2[mi], sb + GU_AL + ao);
            }
#pragma unroll
            for (int mat = 0; mat < 2; mat++) {
                uint32_t bh[4][2], r[4];
#pragma unroll
                for (int g2 = 0; g2 < 2; g2++) {
                    uint32_t bo = (uint32_t)((kk + b_lk) * BPITCH + wn + g2 * 16 + b_ln) * 2;
                    ldsm4t(r, sb + (mat ? GU_B1 : GU_B0) + bo);
                    bh[2*g2][0] = r[0]; bh[2*g2][1] = r[2];
                    bh[2*g2+1][0] = r[1]; bh[2*g2+1][1] = r[3];
                }
                float (*acc)[4][4] = mat ? accu : accg;
#pragma unroll
                for (int mi = 0; mi < 2; mi++)
#pragma unroll
                    for (int ni = 0; ni < 4; ni++) {
                        mma_f16(acc[mi][ni], ah[mi], bh[ni]);
                        mma_f16(acc[mi][ni], al2[mi], bh[ni]);
                    }
            }
        }
        __syncthreads();
        st ^= 1;
    }
#undef GU_LDG
#undef GU_STS

    // epilogue: h = silu(g)*u -> split fp16 (pad rows compute exact zeros)
    int er = lane >> 2, ec = (lane & 3) * 2;
#pragma unroll
    for (int mi = 0; mi < 2; mi++) {
#pragma unroll
        for (int half = 0; half < 2; half++) {
            size_t row = arow0 + m0 + wm + mi * 16 + er + half * 8;
#pragma unroll
            for (int ni = 0; ni < 4; ni++) {
                int c = n0 + wn + ni * 8 + ec;
                float g0 = accg[mi][ni][half*2],     u0 = accu[mi][ni][half*2];
                float g1 = accg[mi][ni][half*2 + 1], u1 = accu[mi][ni][half*2 + 1];
                float f0 = (g0 / (1.f + __expf(-g0))) * u0;
                float f1 = (g1 / (1.f + __expf(-g1))) * u1;
                __half h0, l0, h1, l1;
                split_f16(f0, h0, l0); split_f16(f1, h1, l1);
                *(uint32_t*)(ohh + row * ID + c) = pack2(h0, h1);
                *(uint32_t*)(ohl + row * ID + c) = pack2(l0, l1);
            }
        }
    }
}

// ============================================================================
// GEMM2: down projection, fp16 2-term, double-buffered.
// shared pass writes out; routed pass (after) does +=.
// ============================================================================
__global__ __launch_bounds__(256)
void down_kernel(const float* __restrict__ Wd, float* __restrict__ out, int routed) {
    extern __shared__ char smem[];

    int tid = threadIdx.x, wid = tid >> 5, lane = tid & 31;

    int cnt, obase; size_t arow0;
    const float* wd;
    const __half *axh, *axl;
    if (routed) {
        int e = blockIdx.z;
        obase = g_offsets[e]; cnt = g_offsets[e + 1] - obase;
        wd = Wd + (size_t)e * ID * HD;
        axh = g_hr_hi; axl = g_hr_lo;
        arow0 = (size_t)e * 1024;
    } else {
        obase = 0; cnt = T; wd = Wd;
        axh = g_hs_hi; axl = g_hs_lo;
        arow0 = 0;
    }
    int m0 = blockIdx.x * 128;
    if (m0 >= cnt) return;
    int n0 = blockIdx.y * 64;

    int sa_row = tid >> 1, sa_col = (tid & 1) * 16;
    const __half* pAh = axh + (arow0 + m0 + sa_row) * ID + sa_col;
    const __half* pAl = axl + (arow0 + m0 + sa_row) * ID + sa_col;
    int sb_k = tid >> 3, sb_j = (tid & 7) * 8;
    const float* pW = wd + (size_t)sb_k * HD + n0 + sb_j;
    int a_boff = (sa_row * APITCH + sa_col) * 2;
    int b_boff = (sb_k * BPITCH + sb_j) * 2;

    int wm = (wid >> 1) * 32, wn = (wid & 1) * 32;
    uint32_t sbase = smem_u32(smem);
    int a_lr = lane & 15, a_lc = (lane >> 4) * 8;
    int b_lk = (lane & 7) + (lane >> 4) * 8, b_ln = ((lane >> 3) & 1) * 8;

    float acc[2][4][4] = {};

    uint4 a_h0, a_h1, a_l0, a_l1;
    float4 f_w0, f_w1;
#define DN_LDG(it) { \
    const __half* ph = pAh + (it) * 32; \
    a_h0 = *(const uint4*)ph; a_h1 = *(const uint4*)(ph + 8); \
    const __half* pl = pAl + (it) * 32; \
    a_l0 = *(const uint4*)pl; a_l1 = *(const uint4*)(pl + 8); \
    const float* pw = pW + (size_t)(it) * 32 * HD; \
    f_w0 = *(const float4*)pw; f_w1 = *(const float4*)(pw + 4); }
#define DN_STS(st) { \
    char* base = smem + (st) * DN_SS; \
    *(uint4*)(base + DN_AH + a_boff) = a_h0; \
    *(uint4*)(base + DN_AH + a_boff + 16) = a_h1; \
    *(uint4*)(base + DN_AL + a_boff) = a_l0; \
    *(uint4*)(base + DN_AL + a_boff + 16) = a_l1; \
    cvt8(f_w0, f_w1, (__half*)(base + DN_B + b_boff)); }

    DN_LDG(0);
    DN_STS(0);
    DN_LDG(1);
    __syncthreads();

    int st = 0;
    for (int it = 0; it < NK2; it++) {
        if (it + 1 < NK2) {
            DN_STS(st ^ 1);
            if (it + 2 < NK2) DN_LDG(it + 2);
        }
        uint32_t sb = sbase + st * DN_SS;
#pragma unroll
        for (int kk = 0; kk < 32; kk += 16) {
            uint32_t ah[2][4], al2[2][4];
#pragma unroll
            for (int mi = 0; mi < 2; mi++) {
                uint32_t ao = (uint32_t)((wm + mi * 16 + a_lr) * APITCH + kk + a_lc) * 2;
                ldsm4(ah[mi], sb + DN_AH + ao);
                ldsm4(al2[mi], sb + DN_AL + ao);
            }
            uint32_t bh[4][2], r[4];
#pragma unroll
            for (int g2 = 0; g2 < 2; g2++) {
                uint32_t bo = (uint32_t)((kk + b_lk) * BPITCH + wn + g2 * 16 + b_ln) * 2;
                ldsm4t(r, sb + DN_B + bo);
                bh[2*g2][0] = r[0]; bh[2*g2][1] = r[2];
                bh[2*g2+1][0] = r[1]; bh[2*g2+1][1] = r[3];
            }
#pragma unroll
            for (int mi = 0; mi < 2; mi++)
#pragma unroll
                for (int ni = 0; ni < 4; ni++) {
                    mma_f16(acc[mi][ni], ah[mi], bh[ni]);
                    mma_f16(acc[mi][ni], al2[mi], bh[ni]);
                }
        }
        __syncthreads();
        st ^= 1;
    }
#undef DN_LDG
#undef DN_STS

    int er = lane >> 2, ec = (lane & 3) * 2;
#pragma unroll
    for (int mi = 0; mi < 2; mi++) {
#pragma unroll
        for (int half = 0; half < 2; half++) {
            int gr = m0 + wm + mi * 16 + er + half * 8;
            int token = -1;
            if (gr < cnt) token = routed ? g_perm[obase + gr] : gr;
            if (token >= 0) {
#pragma unroll
                for (int ni = 0; ni < 4; ni++) {
                    int c = n0 + wn + ni * 8 + ec;
                    float2 v = make_float2(acc[mi][ni][half*2], acc[mi][ni][half*2 + 1]);
                    float2* p = (float2*)(out + (size_t)token * HD + c);
                    if (routed) { float2 o = *p; v.x += o.x; v.y += o.y; }
                    *p = v;
                }
            }
        }
    }
}

// ============================================================================
extern "C" void kernel_launch(void* const* d_in, const int* in_sizes, int n_in,
                              void* d_out, int out_size) {
    const float* x        = (const float*)d_in[0];
    const float* w_router = (const float*)d_in[1];
    const float* ws_gate  = (const float*)d_in[2];
    const float* ws_up    = (const float*)d_in[3];
    const float* ws_down  = (const float*)d_in[4];
    const float* we_gate  = (const float*)d_in[5];
    const float* we_up    = (const float*)d_in[6];
    const float* we_down  = (const float*)d_in[7];
    float* out = (float*)d_out;
    (void)in_sizes; (void)n_in; (void)out_size;

    cudaFuncSetAttribute(gateup_kernel, cudaFuncAttributeMaxDynamicSharedMemorySize, GU_BYTES);
    cudaFuncSetAttribute(down_kernel,   cudaFuncAttributeMaxDynamicSharedMemorySize, DN_BYTES);

    router_kernel<<<T / 8, 256>>>(x, w_router);
    perm_kernel<<<1, T>>>();
    presplit_x<<<T * HD / 4 / 256, 256>>>(x);
    gather_kernel<<<dim3(64, E), 256>>>(x);

    gateup_kernel<<<dim3(T / 128, ID / 64, 1), 256, GU_BYTES>>>(ws_gate, ws_up, 0);
    gateup_kernel<<<dim3(T / 128, ID / 64, E), 256, GU_BYTES>>>(we_gate, we_up, 1);

    down_kernel<<<dim3(T / 128, HD / 64, 1), 256, DN_BYTES>>>(ws_down, out, 0);
    down_kernel<<<dim3(T / 128, HD / 64, E), 256, DN_BYTES>>>(we_down, out, 1);
}

// round 10
// speedup vs baseline: 2.3068x; 1.7273x over previous
#include <cuda_runtime.h>
#include <cuda_fp16.h>
#include <cstdint>

#define T  1024
#define HD 2048
#define ID 4096
#define E  8

#define APITCH 40   // fp16 elems; 80B row pitch (conflict-free for ldmatrix)
#define BPITCH 72   // fp16 elems; 144B row pitch
#define NK1 (HD / 32)
#define NK2 (ID / 32)

// double-buffer smem layout (bytes)
#define GU_A   0
#define GU_B0  10240
#define GU_B1  14848
#define GU_SS  19456
#define GU_BYTES (2 * GU_SS)

#define DN_A   0
#define DN_B   10240
#define DN_SS  14848
#define DN_BYTES (2 * DN_SS)

// ---- scratch (single fp16 now) ----
__device__ __half g_x[(size_t)T * HD];
__device__ __half g_xr[(size_t)E * 1024 * HD];
__device__ __half g_hs[(size_t)T * ID];
__device__ __half g_hr[(size_t)E * 1024 * ID];
__device__ int   g_expert[T];
__device__ float g_score[T];
__device__ int   g_perm[T];
__device__ int   g_offsets[E + 1];

// ---- helpers ----
__device__ __forceinline__ uint32_t smem_u32(const void* p) {
    uint32_t a;
    asm("{ .reg .u64 t; cvta.to.shared.u64 t, %1; cvt.u32.u64 %0, t; }" : "=r"(a) : "l"(p));
    return a;
}
__device__ __forceinline__ void ldsm4(uint32_t* r, uint32_t a) {
    asm volatile("ldmatrix.sync.aligned.m8n8.x4.shared.b16 {%0,%1,%2,%3}, [%4];"
                 : "=r"(r[0]), "=r"(r[1]), "=r"(r[2]), "=r"(r[3]) : "r"(a));
}
__device__ __forceinline__ void ldsm4t(uint32_t* r, uint32_t a) {
    asm volatile("ldmatrix.sync.aligned.m8n8.x4.trans.shared.b16 {%0,%1,%2,%3}, [%4];"
                 : "=r"(r[0]), "=r"(r[1]), "=r"(r[2]), "=r"(r[3]) : "r"(a));
}
__device__ __forceinline__ void mma_f16(float* c, const uint32_t* a, const uint32_t* b) {
    asm volatile("mma.sync.aligned.m16n8k16.row.col.f32.f16.f16.f32 "
                 "{%0,%1,%2,%3}, {%4,%5,%6,%7}, {%8,%9}, {%0,%1,%2,%3};"
                 : "+f"(c[0]), "+f"(c[1]), "+f"(c[2]), "+f"(c[3])
                 : "r"(a[0]), "r"(a[1]), "r"(a[2]), "r"(a[3]), "r"(b[0]), "r"(b[1]));
}
__device__ __forceinline__ uint32_t pack2(__half a, __half b) {
    __half2 t = __halves2half2(a, b);
    return *(uint32_t*)&t;
}
__device__ __forceinline__ void cvt8(float4 v0, float4 v1, __half* d) {
    float f[8] = {v0.x, v0.y, v0.z, v0.w, v1.x, v1.y, v1.z, v1.w};
    uint32_t H[4];
#pragma unroll
    for (int i = 0; i < 4; i++)
        H[i] = pack2(__float2half_rn(f[2*i]), __float2half_rn(f[2*i+1]));
    *(uint4*)d = make_uint4(H[0], H[1], H[2], H[3]);
}

// ============================================================================
__global__ void router_kernel(const float* __restrict__ x, const float* __restrict__ wr) {
    int warp = (blockIdx.x * blockDim.x + threadIdx.x) >> 5;
    int lane = threadIdx.x & 31;
    if (warp >= T) return;
    const float* xr = x + (size_t)warp * HD;
    float acc[E];
#pragma unroll
    for (int e = 0; e < E; e++) acc[e] = 0.f;
    for (int h = lane; h < HD; h += 32) {
        float xv = xr[h];
        const float* w = wr + (size_t)h * E;
#pragma unroll
        for (int e = 0; e < E; e++) acc[e] += xv * w[e];
    }
#pragma unroll
    for (int e = 0; e < E; e++) {
#pragma unroll
        for (int o = 16; o; o >>= 1) acc[e] += __shfl_xor_sync(0xffffffffu, acc[e], o);
    }
    if (lane == 0) {
        int best = 0; float bv = acc[0];
#pragma unroll
        for (int e = 1; e < E; e++) if (acc[e] > bv) { bv = acc[e]; best = e; }
        g_expert[warp] = best;
        g_score[warp]  = 1.f / (1.f + __expf(-bv));
    }
}

__global__ void perm_kernel() {
    __shared__ int cnt[E], off[E + 1], cur[E];
    int t = threadIdx.x;
    if (t < E) cnt[t] = 0;
    __syncthreads();
    int e = g_expert[t];
    atomicAdd(&cnt[e], 1);
    __syncthreads();
    if (t == 0) {
        off[0] = 0;
        for (int i = 0; i < E; i++) off[i + 1] = off[i] + cnt[i];
    }
    __syncthreads();
    if (t < E) cur[t] = off[t];
    __syncthreads();
    int pos = atomicAdd(&cur[e], 1);
    g_perm[pos] = t;
    if (t <= E) g_offsets[t] = off[t];
}

__global__ void presplit_x(const float* __restrict__ x) {
    int idx = blockIdx.x * 256 + threadIdx.x;
    float4 v = *(const float4*)(x + (size_t)idx * 4);
    *(uint2*)(g_x + (size_t)idx * 4) = make_uint2(
        pack2(__float2half_rn(v.x), __float2half_rn(v.y)),
        pack2(__float2half_rn(v.z), __float2half_rn(v.w)));
}

__global__ void gather_kernel(const float* __restrict__ x) {
    int e = blockIdx.y;
    int obase = g_offsets[e], cnt = g_offsets[e + 1] - obase;
    int pad = (cnt + 255) & ~255;
    int r0 = blockIdx.x * 16;
    if (r0 >= pad) return;
    for (int idx = threadIdx.x; idx < 16 * HD / 4; idx += 256) {
        int row = idx >> 9;
        int c4  = (idx & 511) * 4;
        int r = r0 + row;
        uint2 hv = make_uint2(0u, 0u);
        if (r < cnt) {
            int tok = g_perm[obase + r];
            float sc = g_score[tok];
            float4 v = *(const float4*)(x + (size_t)tok * HD + c4);
            hv = make_uint2(
                pack2(__float2half_rn(v.x * sc), __float2half_rn(v.y * sc)),
                pack2(__float2half_rn(v.z * sc), __float2half_rn(v.w * sc)));
        }
        *(uint2*)(g_xr + (size_t)(e * 1024 + r) * HD + c4) = hv;
    }
}

// ============================================================================
// GEMM1: h = silu(A@Wg) * (A@Wu). BM=128, BN=64, BK=32; 8 warps (4m x 2n),
// warp tile 32x32 per matrix; single fp16 MMA; double-buffered, 1 sync/tile.
// ============================================================================
__global__ __launch_bounds__(256)
void gateup_kernel(const float* __restrict__ Wg, const float* __restrict__ Wu, int routed) {
    extern __shared__ char smem[];

    int tid = threadIdx.x, wid = tid >> 5, lane = tid & 31;

    int cnt; size_t arow0;
    const float *wg, *wu;
    const __half* ax;
    __half* oh;
    if (routed) {
        int e = blockIdx.z;
        cnt = g_offsets[e + 1] - g_offsets[e];
        wg = Wg + (size_t)e * HD * ID; wu = Wu + (size_t)e * HD * ID;
        ax = g_xr; oh = g_hr;
        arow0 = (size_t)e * 1024;
    } else {
        cnt = T; wg = Wg; wu = Wu;
        ax = g_x; oh = g_hs;
        arow0 = 0;
    }
    int m0 = blockIdx.x * 128;
    if (m0 >= cnt) return;
    int n0 = blockIdx.y * 64;

    int sa_row = tid >> 1, sa_col = (tid & 1) * 16;
    const __half* pA = ax + (arow0 + m0 + sa_row) * HD + sa_col;
    int sb_k = tid >> 3, sb_j = (tid & 7) * 8;
    const float* pG = wg + (size_t)sb_k * ID + n0 + sb_j;
    const float* pU = wu + (size_t)sb_k * ID + n0 + sb_j;
    int a_boff = (sa_row * APITCH + sa_col) * 2;
    int b_boff = (sb_k * BPITCH + sb_j) * 2;

    int wm = (wid >> 1) * 32, wn = (wid & 1) * 32;
    uint32_t sbase = smem_u32(smem);
    int a_lr = lane & 15, a_lc = (lane >> 4) * 8;
    int b_lk = (lane & 7) + (lane >> 4) * 8, b_ln = ((lane >> 3) & 1) * 8;

    float accg[2][4][4] = {}, accu[2][4][4] = {};

    uint4 a_r0, a_r1;
    float4 f_g0, f_g1, f_u0, f_u1;
#define GU_LDG(it) { \
    const __half* ph = pA + (it) * 32; \
    a_r0 = *(const uint4*)ph; a_r1 = *(const uint4*)(ph + 8); \
    const float* pg = pG + (size_t)(it) * 32 * ID; \
    f_g0 = *(const float4*)pg; f_g1 = *(const float4*)(pg + 4); \
    const float* pu = pU + (size_t)(it) * 32 * ID; \
    f_u0 = *(const float4*)pu; f_u1 = *(const float4*)(pu + 4); }
#define GU_STS(st) { \
    char* base = smem + (st) * GU_SS; \
    *(uint4*)(base + GU_A + a_boff) = a_r0; \
    *(uint4*)(base + GU_A + a_boff + 16) = a_r1; \
    cvt8(f_g0, f_g1, (__half*)(base + GU_B0 + b_boff)); \
    cvt8(f_u0, f_u1, (__half*)(base + GU_B1 + b_boff)); }

    GU_LDG(0);
    GU_STS(0);
    GU_LDG(1);
    __syncthreads();

    int st = 0;
    for (int it = 0; it < NK1; it++) {
        if (it + 1 < NK1) {
            GU_STS(st ^ 1);
            if (it + 2 < NK1) GU_LDG(it + 2);
        }
        uint32_t sb = sbase + st * GU_SS;
#pragma unroll
        for (int kk = 0; kk < 32; kk += 16) {
            uint32_t ah[2][4];
#pragma unroll
            for (int mi = 0; mi < 2; mi++) {
                uint32_t ao = (uint32_t)((wm + mi * 16 + a_lr) * APITCH + kk + a_lc) * 2;
                ldsm4(ah[mi], sb + GU_A + ao);
            }
#pragma unroll
            for (int mat = 0; mat < 2; mat++) {
                uint32_t bh[4][2], r[4];
#pragma unroll
                for (int g2 = 0; g2 < 2; g2++) {
                    uint32_t bo = (uint32_t)((kk + b_lk) * BPITCH + wn + g2 * 16 + b_ln) * 2;
                    ldsm4t(r, sb + (mat ? GU_B1 : GU_B0) + bo);
                    bh[2*g2][0] = r[0]; bh[2*g2][1] = r[2];
                    bh[2*g2+1][0] = r[1]; bh[2*g2+1][1] = r[3];
                }
                float (*acc)[4][4] = mat ? accu : accg;
#pragma unroll
                for (int mi = 0; mi < 2; mi++)
#pragma unroll
                    for (int ni = 0; ni < 4; ni++)
                        mma_f16(acc[mi][ni], ah[mi], bh[ni]);
            }
        }
        __syncthreads();
        st ^= 1;
    }
#undef GU_LDG
#undef GU_STS

    // epilogue: h = silu(g)*u -> fp16 (pad rows compute exact zeros)
    int er = lane >> 2, ec = (lane & 3) * 2;
#pragma unroll
    for (int mi = 0; mi < 2; mi++) {
#pragma unroll
        for (int half = 0; half < 2; half++) {
            size_t row = arow0 + m0 + wm + mi * 16 + er + half * 8;
#pragma unroll
            for (int ni = 0; ni < 4; ni++) {
                int c = n0 + wn + ni * 8 + ec;
                float g0 = accg[mi][ni][half*2],     u0 = accu[mi][ni][half*2];
                float g1 = accg[mi][ni][half*2 + 1], u1 = accu[mi][ni][half*2 + 1];
                float f0 = (g0 / (1.f + __expf(-g0))) * u0;
                float f1 = (g1 / (1.f + __expf(-g1))) * u1;
                *(uint32_t*)(oh + row * ID + c) =
                    pack2(__float2half_rn(f0), __float2half_rn(f1));
            }
        }
    }
}

// ============================================================================
// GEMM2: down projection, single fp16 MMA, double-buffered.
// shared pass writes out; routed pass (after) does +=.
// ============================================================================
__global__ __launch_bounds__(256)
void down_kernel(const float* __restrict__ Wd, float* __restrict__ out, int routed) {
    extern __shared__ char smem[];

    int tid = threadIdx.x, wid = tid >> 5, lane = tid & 31;

    int cnt, obase; size_t arow0;
    const float* wd;
    const __half* ax;
    if (routed) {
        int e = blockIdx.z;
        obase = g_offsets[e]; cnt = g_offsets[e + 1] - obase;
        wd = Wd + (size_t)e * ID * HD;
        ax = g_hr;
        arow0 = (size_t)e * 1024;
    } else {
        obase = 0; cnt = T; wd = Wd;
        ax = g_hs;
        arow0 = 0;
    }
    int m0 = blockIdx.x * 128;
    if (m0 >= cnt) return;
    int n0 = blockIdx.y * 64;

    int sa_row = tid >> 1, sa_col = (tid & 1) * 16;
    const __half* pA = ax + (arow0 + m0 + sa_row) * ID + sa_col;
    int sb_k = tid >> 3, sb_j = (tid & 7) * 8;
    const float* pW = wd + (size_t)sb_k * HD + n0 + sb_j;
    int a_boff = (sa_row * APITCH + sa_col) * 2;
    int b_boff = (sb_k * BPITCH + sb_j) * 2;

    int wm = (wid >> 1) * 32, wn = (wid & 1) * 32;
    uint32_t sbase = smem_u32(smem);
    int a_lr = lane & 15, a_lc = (lane >> 4) * 8;
    int b_lk = (lane & 7) + (lane >> 4) * 8, b_ln = ((lane >> 3) & 1) * 8;

    float acc[2][4][4] = {};

    uint4 a_r0, a_r1;
    float4 f_w0, f_w1;
#define DN_LDG(it) { \
    const __half* ph = pA + (it) * 32; \
    a_r0 = *(const uint4*)ph; a_r1 = *(const uint4*)(ph + 8); \
    const float* pw = pW + (size_t)(it) * 32 * HD; \
    f_w0 = *(const float4*)pw; f_w1 = *(const float4*)(pw + 4); }
#define DN_STS(st) { \
    char* base = smem + (st) * DN_SS; \
    *(uint4*)(base + DN_A + a_boff) = a_r0; \
    *(uint4*)(base + DN_A + a_boff + 16) = a_r1; \
    cvt8(f_w0, f_w1, (__half*)(base + DN_B + b_boff)); }

    DN_LDG(0);
    DN_STS(0);
    DN_LDG(1);
    __syncthreads();

    int st = 0;
    for (int it = 0; it < NK2; it++) {
        if (it + 1 < NK2) {
            DN_STS(st ^ 1);
            if (it + 2 < NK2) DN_LDG(it + 2);
        }
        uint32_t sb = sbase + st * DN_SS;
#pragma unroll
        for (int kk = 0; kk < 32; kk += 16) {
            uint32_t ah[2][4];
#pragma unroll
            for (int mi = 0; mi < 2; mi++) {
                uint32_t ao = (uint32_t)((wm + mi * 16 + a_lr) * APITCH + kk + a_lc) * 2;
                ldsm4(ah[mi], sb + DN_A + ao);
            }
            uint32_t bh[4][2], r[4];
#pragma unroll
            for (int g2 = 0; g2 < 2; g2++) {
                uint32_t bo = (uint32_t)((kk + b_lk) * BPITCH + wn + g2 * 16 + b_ln) * 2;
                ldsm4t(r, sb + DN_B + bo);
                bh[2*g2][0] = r[0]; bh[2*g2][1] = r[2];
                bh[2*g2+1][0] = r[1]; bh[2*g2+1][1] = r[3];
            }
#pragma unroll
            for (int mi = 0; mi < 2; mi++)
#pragma unroll
                for (int ni = 0; ni < 4; ni++)
                    mma_f16(acc[mi][ni], ah[mi], bh[ni]);
        }
        __syncthreads();
        st ^= 1;
    }
#undef DN_LDG
#undef DN_STS

    int er = lane >> 2, ec = (lane & 3) * 2;
#pragma unroll
    for (int mi = 0; mi < 2; mi++) {
#pragma unroll
        for (int half = 0; half < 2; half++) {
            int gr = m0 + wm + mi * 16 + er + half * 8;
            int token = -1;
            if (gr < cnt) token = routed ? g_perm[obase + gr] : gr;
            if (token >= 0) {
#pragma unroll
                for (int ni = 0; ni < 4; ni++) {
                    int c = n0 + wn + ni * 8 + ec;
                    float2 v = make_float2(acc[mi][ni][half*2], acc[mi][ni][half*2 + 1]);
                    float2* p = (float2*)(out + (size_t)token * HD + c);
                    if (routed) { float2 o = *p; v.x += o.x; v.y += o.y; }
                    *p = v;
                }
            }
        }
    }
}

// ============================================================================
extern "C" void kernel_launch(void* const* d_in, const int* in_sizes, int n_in,
                              void* d_out, int out_size) {
    const float* x        = (const float*)d_in[0];
    const float* w_router = (const float*)d_in[1];
    const float* ws_gate  = (const float*)d_in[2];
    const float* ws_up    = (const float*)d_in[3];
    const float* ws_down  = (const float*)d_in[4];
    const float* we_gate  = (const float*)d_in[5];
    const float* we_up    = (const float*)d_in[6];
    const float* we_down  = (const float*)d_in[7];
    float* out = (float*)d_out;
    (void)in_sizes; (void)n_in; (void)out_size;

    cudaFuncSetAttribute(gateup_kernel, cudaFuncAttributeMaxDynamicSharedMemorySize, GU_BYTES);
    cudaFuncSetAttribute(down_kernel,   cudaFuncAttributeMaxDynamicSharedMemorySize, DN_BYTES);

    router_kernel<<<T / 8, 256>>>(x, w_router);
    perm_kernel<<<1, T>>>();
    presplit_x<<<T * HD / 4 / 256, 256>>>(x);
    gather_kernel<<<dim3(64, E), 256>>>(x);

    gateup_kernel<<<dim3(T / 128, ID / 64, 1), 256, GU_BYTES>>>(ws_gate, ws_up, 0);
    gateup_kernel<<<dim3(T / 128, ID / 64, E), 256, GU_BYTES>>>(we_gate, we_up, 1);

    down_kernel<<<dim3(T / 128, HD / 64, 1), 256, DN_BYTES>>>(ws_down, out, 0);
    down_kernel<<<dim3(T / 128, HD / 64, E), 256, DN_BYTES>>>(we_down, out, 1);
}